// round 1
// baseline (speedup 1.0000x reference)
#include <cuda_runtime.h>

// Pair_83811991814342
// in:  (1, 1024, 260) fp32; only first 512 rows used
// out: (1, 512*512, 522) fp32 : [x[i](260) | x[j](260) | r1 | r2]
// r1 = inter(i,j)/area(i), r2 = inter(i,j)/area(j), bbox = last 4 feats.

#define NROWS 512
#define DIM   260
#define HDIM  (DIM / 2)      // 130 float2 per source row
#define HC    261            // float2 per output row (522/2)
#define TI    8
#define TJ    8
#define NT    256

__global__ __launch_bounds__(NT)
void pair_kernel(const float* __restrict__ in, float* __restrict__ out) {
    // 16 source rows cached in smem, float4-packed (row = 65 float4 = 1040 B)
    __shared__ float4 sx4[TI + TJ][DIM / 4];

    const int bi = blockIdx.y * TI;
    const int bj = blockIdx.x * TJ;

    // Load the TI i-rows and TJ j-rows (float4 vectorized; 1040B rows are 16B aligned)
    for (int t = threadIdx.x; t < (TI + TJ) * (DIM / 4); t += NT) {
        int r = t / (DIM / 4);
        int c = t - r * (DIM / 4);
        int g = (r < TI) ? (bi + r) : (bj + (r - TI));
        sx4[r][c] = reinterpret_cast<const float4*>(in)[g * (DIM / 4) + c];
    }
    __syncthreads();

    // 64 output rows per block, 261 float2 each. Flattened for load balance.
    for (int idx = threadIdx.x; idx < TI * TJ * HC; idx += NT) {
        int rr = idx / HC;          // tile-local row [0,64)
        int c  = idx - rr * HC;     // float2 column [0,261)
        int il = rr >> 3;           // rr / TJ
        int jl = rr & (TJ - 1);     // rr % TJ

        const float2* si = reinterpret_cast<const float2*>(sx4[il]);
        const float2* sj = reinterpret_cast<const float2*>(sx4[TI + jl]);

        float2 v;
        if (c < HDIM) {
            v = si[c];                      // x[i] floats [2c, 2c+1]
        } else if (c < DIM) {
            v = sj[c - HDIM];               // x[j] floats [2(c-130), ...]
        } else {
            // c == 260: (r1, r2)
            const float* fi = reinterpret_cast<const float*>(sx4[il]);
            const float* fj = reinterpret_cast<const float*>(sx4[TI + jl]);
            float x1i = fi[DIM - 4], y1i = fi[DIM - 3], x2i = fi[DIM - 2], y2i = fi[DIM - 1];
            float x1j = fj[DIM - 4], y1j = fj[DIM - 3], x2j = fj[DIM - 2], y2j = fj[DIM - 1];
            float w = fmaxf(0.0f, fminf(x2i, x2j) - fmaxf(x1i, x1j));
            float h = fmaxf(0.0f, fminf(y2i, y2j) - fmaxf(y1i, y1j));
            float inter = w * h;
            float ai = (x2i - x1i) * (y2i - y1i);
            float aj = (x2j - x1j) * (y2j - y1j);
            v = make_float2(inter / ai, inter / aj);
        }

        size_t orow = (size_t)(bi + il) * NROWS + (size_t)(bj + jl);
        reinterpret_cast<float2*>(out)[orow * HC + c] = v;
    }
}

extern "C" void kernel_launch(void* const* d_in, const int* in_sizes, int n_in,
                              void* d_out, int out_size) {
    const float* in = (const float*)d_in[0];
    float* out = (float*)d_out;
    dim3 grid(NROWS / TJ, NROWS / TI);  // 64 x 64 blocks
    pair_kernel<<<grid, NT>>>(in, out);
}

// round 3
// speedup vs baseline: 1.1400x; 1.1400x over previous
#include <cuda_runtime.h>

// Pair_83811991814342
// in:  (1, 1024, 260) fp32; only first 512 rows used
// out: (1, 512*512, 522) fp32 : [x[i](260) | x[j](260) | r1 | r2]

#define NROWS 512
#define DIM   260
#define HD    130            // float2 per input row
#define HC    261            // float2 per output row (522/2)
#define TI    8
#define TJ    8
#define NT    288            // 261 active column threads + r1r2 helper slack

__global__ __launch_bounds__(NT)
void pair_kernel(const float* __restrict__ in, float* __restrict__ out) {
    __shared__ float2 s_r[TI * TJ];     // (r1, r2) for each pair in the tile

    const int bi = blockIdx.y * TI;
    const int bj = blockIdx.x * TJ;
    const int c  = threadIdx.x;         // float2 column in output row

    // ---- Precompute (r1, r2) for all 64 pairs (threads 0..63) ----
    if (c < TI * TJ) {
        int il = c >> 3, jl = c & 7;
        const float* fi = in + (bi + il) * DIM + (DIM - 4);
        const float* fj = in + (bj + jl) * DIM + (DIM - 4);
        float x1i = fi[0], y1i = fi[1], x2i = fi[2], y2i = fi[3];
        float x1j = fj[0], y1j = fj[1], x2j = fj[2], y2j = fj[3];
        float w = fmaxf(0.0f, fminf(x2i, x2j) - fmaxf(x1i, x1j));
        float h = fmaxf(0.0f, fminf(y2i, y2j) - fmaxf(y1i, y1j));
        float inter = w * h;
        float ai = (x2i - x1i) * (y2i - y1i);
        float aj = (x2j - x1j) * (y2j - y1j);
        s_r[c] = make_float2(inter / ai, inter / aj);
    }

    // ---- Preload this thread's column from the 8 relevant source rows ----
    const bool lo  = (c < HD);          // column belongs to x[i] part
    const bool mid = (c < 2 * HD);      // data column (vs r1r2 column 260)
    float2 v[8];
    if (mid) {
        const float2* src = reinterpret_cast<const float2*>(in)
                          + (lo ? (bi * HD + c) : (bj * HD + (c - HD)));
        #pragma unroll
        for (int r = 0; r < 8; r++) v[r] = src[r * HD];
    }
    __syncthreads();

    // ---- 64 stores, fully unrolled: SEL + STG.64 with immediate offsets ----
    if (c <= 2 * HD) {                  // c < 261
        float2* ob = reinterpret_cast<float2*>(out)
                   + (size_t)(bi * NROWS + bj) * HC + c;
        #pragma unroll
        for (int il = 0; il < TI; il++) {
            #pragma unroll
            for (int jl = 0; jl < TJ; jl++) {
                float2 val = lo ? v[il] : v[jl];
                if (!mid) val = s_r[(il << 3) | jl];   // only thread c==260
                ob[(size_t)(il * NROWS + jl) * HC] = val;
            }
        }
    }
}

extern "C" void kernel_launch(void* const* d_in, const int* in_sizes, int n_in,
                              void* d_out, int out_size) {
    const float* in = (const float*)d_in[0];
    float* out = (float*)d_out;
    dim3 grid(NROWS / TJ, NROWS / TI);  // 64 x 64 blocks
    pair_kernel<<<grid, NT>>>(in, out);
}